// round 15
// baseline (speedup 1.0000x reference)
#include <cuda_runtime.h>
#include <cstdint>
#include <math.h>

#define BB 32
#define NN 256
#define HH 12
#define DD 64
#define CC 768

// ---------------- scratch (device globals; no runtime allocation) ----------------
__device__ float g_qin[BB*HH*NN*DD];      // (b,h,n,d)
__device__ float g_kin[BB*HH*NN*DD];      // (b,h,n,d)
__device__ float g_vt [BB*HH*DD*NN];      // (b,h,d,m)  V^T for PV GEMM
__device__ float g_qgr[BB*NN*CC];         // (b,n,h*64+d)
__device__ float g_kgr[BB*NN*CC];         // (b,n,h*64+d)
__device__ float g_sq [(size_t)BB*HH*NN*NN]; // gs*dots^2  (b,h,n,m)
__device__ float g_mix[(size_t)BB*HH*NN*NN]; // softmaxed P (b,o,n,m)
__device__ float g_ctx[BB*NN*CC];         // (b,n,h*64+d)
__device__ float g_dummy[2];              // sink for launch-slot shift kernels

__device__ __forceinline__ float tf32_rna(float f) {
    uint32_t o;
    asm("cvt.rna.tf32.f32 %0, %1;" : "=r"(o) : "f"(f));
    return __uint_as_float(o);
}

__device__ __forceinline__ void mma_tf32(float* c, const float* a, const float* b) {
    asm volatile(
        "mma.sync.aligned.m16n8k8.row.col.f32.tf32.tf32.f32 "
        "{%0,%1,%2,%3}, {%4,%5,%6,%7}, {%8,%9}, {%0,%1,%2,%3};"
        : "+f"(c[0]), "+f"(c[1]), "+f"(c[2]), "+f"(c[3])
        : "r"(__float_as_uint(a[0])), "r"(__float_as_uint(a[1])),
          "r"(__float_as_uint(a[2])), "r"(__float_as_uint(a[3])),
          "r"(__float_as_uint(b[0])), "r"(__float_as_uint(b[1])));
}

// Launch-slot shift kernels (deterministic, allocation-free, ~1 µs each).
__global__ void dummy_kernel_a() { g_dummy[0] = 1.0f; }
__global__ void dummy_kernel_b() { g_dummy[1] = 1.0f; }

// ======================= TF32 mma.sync GEMM (R3 structure — proven fast) =======================
template<int MODE, int TN, int NCH>
__global__ void __launch_bounds__(256) gemm_mma(const float* __restrict__ Ain,
                                                const float* __restrict__ Bin,
                                                const float* __restrict__ Xtra,
                                                float* __restrict__ Og)
{
    __shared__ float As[128 * 20];
    __shared__ float Bs[TN * 20];
    constexpr int NF = TN / 16;
    constexpr int NB4 = (TN * 4) / 256;

    const int tid = threadIdx.x, lane = tid & 31, wid = tid >> 5;
    const int wm = wid >> 1, wn = wid & 1;

    const float* Aba; const float* Bba; int sA, sB;
    if (MODE == 0) {
        Aba = Ain + (size_t)blockIdx.y * 128 * 768; sA = 768;
        Bba = Bin + (size_t)blockIdx.x * 128 * 768; sB = 768;
    } else if (MODE == 1) {
        int b = blockIdx.z, h = blockIdx.y;
        int nt = blockIdx.x >> 1, mt = blockIdx.x & 1;
        Aba = g_qgr + ((size_t)(b * 256 + nt * 128)) * 768 + h * 64; sA = 768;
        Bba = g_kgr + ((size_t)(b * 256 + mt * 128)) * 768 + h * 64; sB = 768;
    } else if (MODE == 2) {
        Aba = g_mix + (size_t)blockIdx.y * 65536 + (size_t)blockIdx.x * 128 * 256; sA = 256;
        Bba = g_vt + (size_t)blockIdx.y * 16384; sB = 256;
    } else {
        Aba = g_ctx + (size_t)blockIdx.y * 128 * 768; sA = 768;
        Bba = Bin + (size_t)blockIdx.x * 128 * 768; sB = 768;
    }

    float c[2][NF][4];
#pragma unroll
    for (int mf = 0; mf < 2; mf++)
#pragma unroll
        for (int nf = 0; nf < NF; nf++)
#pragma unroll
            for (int e = 0; e < 4; e++) c[mf][nf][e] = 0.f;

    float4 ra[2], rb[NB4];

#pragma unroll
    for (int i = 0; i < 2; i++) {
        int f = tid + i * 256; int r = f >> 2, cc = (f & 3) * 4;
        ra[i] = *(const float4*)(Aba + (size_t)r * sA + cc);
    }
#pragma unroll
    for (int i = 0; i < NB4; i++) {
        int f = tid + i * 256; int r = f >> 2, cc = (f & 3) * 4;
        rb[i] = *(const float4*)(Bba + (size_t)r * sB + cc);
    }

    for (int ch = 0; ch < NCH; ch++) {
#pragma unroll
        for (int i = 0; i < 2; i++) {
            int f = tid + i * 256; int r = f >> 2, cc = (f & 3) * 4;
            float4 v = ra[i];
            v.x = tf32_rna(v.x); v.y = tf32_rna(v.y); v.z = tf32_rna(v.z); v.w = tf32_rna(v.w);
            *(float4*)&As[r * 20 + cc] = v;
        }
#pragma unroll
        for (int i = 0; i < NB4; i++) {
            int f = tid + i * 256; int r = f >> 2, cc = (f & 3) * 4;
            float4 v = rb[i];
            v.x = tf32_rna(v.x); v.y = tf32_rna(v.y); v.z = tf32_rna(v.z); v.w = tf32_rna(v.w);
            *(float4*)&Bs[r * 20 + cc] = v;
        }
        __syncthreads();

        if (ch + 1 < NCH) {
            int ko = (ch + 1) * 16;
#pragma unroll
            for (int i = 0; i < 2; i++) {
                int f = tid + i * 256; int r = f >> 2, cc = (f & 3) * 4;
                ra[i] = *(const float4*)(Aba + (size_t)r * sA + ko + cc);
            }
#pragma unroll
            for (int i = 0; i < NB4; i++) {
                int f = tid + i * 256; int r = f >> 2, cc = (f & 3) * 4;
                rb[i] = *(const float4*)(Bba + (size_t)r * sB + ko + cc);
            }
        }

#pragma unroll
        for (int kk = 0; kk < 2; kk++) {
            const int ko = kk * 8;
            float a[2][4];
#pragma unroll
            for (int mf = 0; mf < 2; mf++) {
                int r0 = wm * 32 + mf * 16 + (lane >> 2);
                a[mf][0] = As[r0 * 20 + ko + (lane & 3)];
                a[mf][1] = As[(r0 + 8) * 20 + ko + (lane & 3)];
                a[mf][2] = As[r0 * 20 + ko + 4 + (lane & 3)];
                a[mf][3] = As[(r0 + 8) * 20 + ko + 4 + (lane & 3)];
            }
            float b[NF][2];
#pragma unroll
            for (int nf = 0; nf < NF; nf++) {
                int rr = wn * (TN / 2) + nf * 8 + (lane >> 2);
                b[nf][0] = Bs[rr * 20 + ko + (lane & 3)];
                b[nf][1] = Bs[rr * 20 + ko + 4 + (lane & 3)];
            }
#pragma unroll
            for (int mf = 0; mf < 2; mf++)
#pragma unroll
                for (int nf = 0; nf < NF; nf++)
                    mma_tf32(c[mf][nf], a[mf], b[nf]);
        }
        __syncthreads();
    }

#pragma unroll
    for (int mf = 0; mf < 2; mf++) {
#pragma unroll
        for (int nf = 0; nf < NF; nf++) {
            int rib0 = wm * 32 + mf * 16 + (lane >> 2);
            int cib = wn * (TN / 2) + nf * 8 + 2 * (lane & 3);
#pragma unroll
            for (int e = 0; e < 2; e++) {
                int rib = rib0 + e * 8;
                float v0 = c[mf][nf][e * 2], v1 = c[mf][nf][e * 2 + 1];
                if (MODE == 0) {
                    int colg = blockIdx.x * 128 + cib;
                    int rowg = blockIdx.y * 128 + rib;
                    int b = rowg >> 8, n = rowg & 255;
                    int which = colg / 768;
                    int rr = colg - which * 768;
                    int h = rr >> 6, dd = rr & 63;
                    v0 += Xtra[colg]; v1 += Xtra[colg + 1];
                    if (which == 0)
                        *(float2*)&g_qin[(((size_t)(b * 12 + h) * 256) + n) * 64 + dd] = make_float2(v0, v1);
                    else if (which == 1)
                        *(float2*)&g_kin[(((size_t)(b * 12 + h) * 256) + n) * 64 + dd] = make_float2(v0, v1);
                    else {
                        g_vt[(((size_t)(b * 12 + h)) * 64 + dd) * 256 + n] = v0;
                        g_vt[(((size_t)(b * 12 + h)) * 64 + dd + 1) * 256 + n] = v1;
                    }
                } else if (MODE == 1) {
                    float gs = Xtra[0];
                    int b = blockIdx.z, h = blockIdx.y;
                    int nt = blockIdx.x >> 1, mt = blockIdx.x & 1;
                    int n = nt * 128 + rib;
                    int m = mt * 128 + cib;
                    v0 = v0 * v0 * gs; v1 = v1 * v1 * gs;
                    *(float2*)&g_sq[(((size_t)(b * 12 + h) * 256) + n) * 256 + m] = make_float2(v0, v1);
                } else if (MODE == 2) {
                    int bh = blockIdx.y; int b = bh / 12, h = bh - b * 12;
                    int n = blockIdx.x * 128 + rib;
                    *(float2*)&g_ctx[((size_t)(b * 256 + n)) * 768 + h * 64 + cib] = make_float2(v0, v1);
                } else {
                    int colg = blockIdx.x * 128 + cib;
                    int rowg = blockIdx.y * 128 + rib;
                    v0 += Xtra[colg]; v1 += Xtra[colg + 1];
                    *(float2*)&Og[(size_t)rowg * 768 + colg] = make_float2(v0, v1);
                }
            }
        }
    }
}

// =====================================================================
// Batched Householder QR — rank-2 pairs with 2-column-batched trailing
// updates (R14 — current best structure, byte-identical).
// =====================================================================
__global__ void __launch_bounds__(256) qr_kernel()
{
    extern __shared__ float sA[];   // 64 * 257
    __shared__ float s_tau[64];
    __shared__ float s_red[8];
    __shared__ float s_red2[8];
    __shared__ float s_alpha, s_vjp;

    const int tid = threadIdx.x;
    const int lane = tid & 31, warp = tid >> 5;

    int slab = blockIdx.x;
    int isk = (slab >= 384) ? 1 : 0;
    int s = slab - isk * 384;
    const float* src = (isk ? g_kin : g_qin) + (size_t)s * NN * DD;
    float* dst = isk ? g_kgr : g_qgr;
    int b = s / 12, h = s % 12;

    for (int idx = tid; idx < NN * DD; idx += 256) {
        int r = idx >> 6, c = idx & 63;
        sA[c * 257 + r] = src[idx];
    }
    __syncthreads();

    // ---------------- geqrf (pairs j, j+1) ----------------
    for (int j = 0; j < 64; j += 2) {
        float* colj  = sA + j * 257;
        float* colj1 = colj + 257;

        float x = (tid >= j) ? colj[tid] : 0.f;
        float alpha = colj[j];
        float ss = x * x;
#pragma unroll
        for (int o = 16; o > 0; o >>= 1) ss += __shfl_xor_sync(0xffffffffu, ss, o);
        if (lane == 0) s_red[warp] = ss;
        __syncthreads();
        float tot = 0.f;
#pragma unroll
        for (int w = 0; w < 8; w++) tot += s_red[w];
        float norm = sqrtf(tot);
        float tauj, scalj;
        if (norm < 1e-30f) { tauj = 0.f; scalj = 0.f; }
        else {
            float beta = (alpha >= 0.f) ? -norm : norm;
            tauj = (beta - alpha) / beta;
            scalj = 1.f / (alpha - beta);
        }
        if (tid == 0) s_tau[j] = tauj;
        if (tid > j)       colj[tid] = x * scalj;
        else if (tid == j) colj[tid] = 1.f;
        __syncthreads();

        float vj = colj[tid];
        float a1 = colj1[tid];
        float pd = (tid >= j) ? vj * a1 : 0.f;
#pragma unroll
        for (int o = 16; o > 0; o >>= 1) pd += __shfl_xor_sync(0xffffffffu, pd, o);
        if (lane == 0) s_red[warp] = pd;
        __syncthreads();
        float d1 = 0.f;
#pragma unroll
        for (int w = 0; w < 8; w++) d1 += s_red[w];
        float a1n = (tid >= j) ? a1 - tauj * d1 * vj : a1;
        float y  = (tid >= j + 1) ? a1n : 0.f;
        float ss2 = y * y;
        float sv  = (tid >= j + 1) ? vj * a1n : 0.f;
#pragma unroll
        for (int o = 16; o > 0; o >>= 1) {
            ss2 += __shfl_xor_sync(0xffffffffu, ss2, o);
            sv  += __shfl_xor_sync(0xffffffffu, sv, o);
        }
        if (lane == 0) { s_red[warp] = ss2; s_red2[warp] = sv; }
        if (tid == j + 1) { s_alpha = a1n; s_vjp = vj; }
        __syncthreads();
        float tot2 = 0.f, svs = 0.f;
#pragma unroll
        for (int w = 0; w < 8; w++) { tot2 += s_red[w]; svs += s_red2[w]; }
        float alpha2 = s_alpha, vjp = s_vjp;
        float norm2 = sqrtf(tot2);
        float tau1, scal1;
        if (norm2 < 1e-30f) { tau1 = 0.f; scal1 = 0.f; }
        else {
            float beta2 = (alpha2 >= 0.f) ? -norm2 : norm2;
            tau1 = (beta2 - alpha2) / beta2;
            scal1 = 1.f / (alpha2 - beta2);
        }
        if (tid == 0) s_tau[j + 1] = tau1;
        float s12 = vjp + scal1 * (svs - vjp * alpha2);
        float nv1;
        if (tid < j + 1)       nv1 = a1n;
        else if (tid == j + 1) nv1 = 1.f;
        else                   nv1 = a1n * scal1;
        colj1[tid] = nv1;
        __syncthreads();

        for (int c0 = j + 2 + warp * 2; c0 < 64; c0 += 16) {
            float vja[8], v1a[8];
#pragma unroll
            for (int k = 0; k < 8; k++) {
                int r = lane + k * 32;
                vja[k] = colj[r]; v1a[k] = colj1[r];
            }
            const int c1i = (c0 + 1 < 64) ? c0 + 1 : c0;
            const float* colcA = sA + c0 * 257;
            const float* colcB = sA + c1i * 257;
            float avA[8], avB[8];
            float d1A = 0.f, d2A = 0.f, d1B = 0.f, d2B = 0.f;
#pragma unroll
            for (int k = 0; k < 8; k++) {
                int r = lane + k * 32;
                avA[k] = colcA[r];
                avB[k] = colcB[r];
                if (r >= j)     { d1A += vja[k] * avA[k]; d1B += vja[k] * avB[k]; }
                if (r >= j + 1) { d2A += v1a[k] * avA[k]; d2B += v1a[k] * avB[k]; }
            }
#pragma unroll
            for (int o = 16; o > 0; o >>= 1) {
                d1A += __shfl_xor_sync(0xffffffffu, d1A, o);
                d2A += __shfl_xor_sync(0xffffffffu, d2A, o);
                d1B += __shfl_xor_sync(0xffffffffu, d1B, o);
                d2B += __shfl_xor_sync(0xffffffffu, d2B, o);
            }
            {
                float c1 = tauj * d1A;
                float c2 = tau1 * (d2A - c1 * s12);
                float* colc = sA + c0 * 257;
#pragma unroll
                for (int k = 0; k < 8; k++) {
                    int r = lane + k * 32;
                    if (r >= j) {
                        float nv = avA[k] - c1 * vja[k];
                        if (r >= j + 1) nv -= c2 * v1a[k];
                        colc[r] = nv;
                    }
                }
            }
            if (c0 + 1 < 64) {
                float c1 = tauj * d1B;
                float c2 = tau1 * (d2B - c1 * s12);
                float* colc = sA + (c0 + 1) * 257;
#pragma unroll
                for (int k = 0; k < 8; k++) {
                    int r = lane + k * 32;
                    if (r >= j) {
                        float nv = avB[k] - c1 * vja[k];
                        if (r >= j + 1) nv -= c2 * v1a[k];
                        colc[r] = nv;
                    }
                }
            }
        }
        __syncthreads();
    }

    // ---------------- org2r (pairs i, i-1) ----------------
    for (int i = 63; i >= 1; i -= 2) {
        float* coli  = sA + i * 257;
        float* coli1 = coli - 257;
        float taui = s_tau[i], tau1 = s_tau[i - 1];

        int r = tid;
        float vi = coli[r];
        float v1 = coli1[r];
        float sp = (r >= i) ? v1 * vi : 0.f;
        float q;
        if (r < i) q = 0.f; else if (r == i) q = 1.f - taui; else q = -taui * vi;
        float qd = (r >= i) ? v1 * q : 0.f;
#pragma unroll
        for (int o = 16; o > 0; o >>= 1) {
            sp += __shfl_xor_sync(0xffffffffu, sp, o);
            qd += __shfl_xor_sync(0xffffffffu, qd, o);
        }
        if (lane == 0) { s_red[warp] = sp; s_red2[warp] = qd; }
        __syncthreads();
        float s12 = 0.f, dq = 0.f;
#pragma unroll
        for (int w = 0; w < 8; w++) { s12 += s_red[w]; dq += s_red2[w]; }

        for (int c0 = i + 1 + warp * 2; c0 < 64; c0 += 16) {
            float via[8], v1a[8];
#pragma unroll
            for (int k = 0; k < 8; k++) {
                int rr = lane + k * 32;
                via[k] = coli[rr]; v1a[k] = coli1[rr];
            }
            const int c1i = (c0 + 1 < 64) ? c0 + 1 : c0;
            const float* colcA = sA + c0 * 257;
            const float* colcB = sA + c1i * 257;
            float avA[8], avB[8];
            float diA = 0.f, dmA = 0.f, diB = 0.f, dmB = 0.f;
#pragma unroll
            for (int k = 0; k < 8; k++) {
                int rr = lane + k * 32;
                avA[k] = colcA[rr];
                avB[k] = colcB[rr];
                if (rr >= i)     { diA += via[k] * avA[k]; diB += via[k] * avB[k]; }
                if (rr >= i - 1) { dmA += v1a[k] * avA[k]; dmB += v1a[k] * avB[k]; }
            }
#pragma unroll
            for (int o = 16; o > 0; o >>= 1) {
                diA += __shfl_xor_sync(0xffffffffu, diA, o);
                dmA += __shfl_xor_sync(0xffffffffu, dmA, o);
                diB += __shfl_xor_sync(0xffffffffu, diB, o);
                dmB += __shfl_xor_sync(0xffffffffu, dmB, o);
            }
            {
                float c1 = taui * diA;
                float c2 = tau1 * (dmA - c1 * s12);
                float* colc = sA + c0 * 257;
#pragma unroll
                for (int k = 0; k < 8; k++) {
                    int rr = lane + k * 32;
                    if (rr >= i - 1) {
                        float nv = avA[k] - c2 * v1a[k];
                        if (rr >= i) nv -= c1 * via[k];
                        colc[rr] = nv;
                    }
                }
            }
            if (c0 + 1 < 64) {
                float c1 = taui * diB;
                float c2 = tau1 * (dmB - c1 * s12);
                float* colc = sA + (c0 + 1) * 257;
#pragma unroll
                for (int k = 0; k < 8; k++) {
                    int rr = lane + k * 32;
                    if (rr >= i - 1) {
                        float nv = avB[k] - c2 * v1a[k];
                        if (rr >= i) nv -= c1 * via[k];
                        colc[rr] = nv;
                    }
                }
            }
        }
        __syncthreads();

        float qn = q;
        if (r >= i - 1) qn -= tau1 * dq * v1;
        coli[r] = qn;
        float nv;
        if (r < i - 1)       nv = 0.f;
        else if (r == i - 1) nv = 1.f - tau1;
        else                 nv = -tau1 * v1;
        coli1[r] = nv;
        __syncthreads();
    }

    for (int idx = tid; idx < NN * DD; idx += 256) {
        int r = idx >> 6, c = idx & 63;
        dst[(size_t)(b * 256 + r) * 768 + h * 64 + c] = sA[c * 257 + r];
    }
}

// =====================================================================
// Fused channel-mix + softmax. Block handles (b, 2 n-rows), 512 threads.
// =====================================================================
__global__ void __launch_bounds__(512) mixsoftmax_kernel(const float* __restrict__ conv_w,
                                                         const float* __restrict__ conv_b)
{
    __shared__ float sm[24][260];
    __shared__ float s_w2[12][12];
    __shared__ float s_cb[12];

    int tid = threadIdx.x;
    int b = blockIdx.y;
    int n0 = blockIdx.x * 2;

    if (tid < 144) {
        int o = tid / 12, h = tid % 12;
        s_w2[o][h] = conv_w[o * 24 + h] + conv_w[o * 24 + 12 + h];
    }
    if (tid < 12) s_cb[tid] = conv_b[tid];
    __syncthreads();

    {
        int nn = tid >> 8, m = tid & 255;
        float v[12];
#pragma unroll
        for (int h = 0; h < 12; h++)
            v[h] = g_sq[(((size_t)(b * 12 + h) * 256) + n0 + nn) * 256 + m];
#pragma unroll
        for (int o = 0; o < 12; o++) {
            float acc = s_cb[o];
#pragma unroll
            for (int h = 0; h < 12; h++) acc += s_w2[o][h] * v[h];
            sm[nn * 12 + o][m] = acc;
        }
    }
    __syncthreads();

    int warp = tid >> 5, lane = tid & 31;
    for (int row = warp; row < 24; row += 16) {
        int nn = row / 12, o = row - nn * 12;
        const float* src = sm[row];
        float v[8];
        float mx = -1e30f;
#pragma unroll
        for (int i = 0; i < 8; i++) { v[i] = src[i * 32 + lane]; mx = fmaxf(mx, v[i]); }
#pragma unroll
        for (int off = 16; off > 0; off >>= 1) mx = fmaxf(mx, __shfl_xor_sync(0xffffffffu, mx, off));
        float smv = 0.f;
#pragma unroll
        for (int i = 0; i < 8; i++) { v[i] = expf(v[i] - mx); smv += v[i]; }
#pragma unroll
        for (int off = 16; off > 0; off >>= 1) smv += __shfl_xor_sync(0xffffffffu, smv, off);
        float inv = 1.f / smv;
        float* dstp = g_mix + (((size_t)(b * 12 + o) * 256) + n0 + nn) * 256;
#pragma unroll
        for (int i = 0; i < 8; i++) dstp[i * 32 + lane] = v[i] * inv;
    }
}

// =====================================================================
extern "C" void kernel_launch(void* const* d_in, const int* in_sizes, int n_in,
                              void* d_out, int out_size)
{
    const float* x      = (const float*)d_in[0];
    const float* qkv_w  = (const float*)d_in[1];
    const float* qkv_b  = (const float*)d_in[2];
    const float* gscale = (const float*)d_in[3];
    const float* conv_w = (const float*)d_in[4];
    const float* conv_b = (const float*)d_in[5];
    const float* proj_w = (const float*)d_in[6];
    const float* proj_b = (const float*)d_in[7];
    float* out = (float*)d_out;

    cudaFuncSetAttribute(qr_kernel, cudaFuncAttributeMaxDynamicSharedMemorySize, 64 * 257 * 4);

    // 1) QKV projection + scatter  (M=8192, N=2304, K=768)
    gemm_mma<0, 128, 48><<<dim3(18, 64), 256>>>(x, qkv_w, qkv_b, nullptr);
    // 1.5) launch-slot shift so ncu's fixed capture index lands on qr_kernel
    dummy_kernel_a<<<1, 1>>>();
    dummy_kernel_b<<<1, 1>>>();
    // 2) batched Householder QR (768 slabs of 256x64), rank-2 pairs + 2-col batches
    qr_kernel<<<768, 256, 64 * 257 * 4>>>();
    // 3) Grassmann dots, squared+scaled  (per (b,h): 256x256x64)
    gemm_mma<1, 128, 4><<<dim3(4, 12, 32), 256>>>(nullptr, nullptr, gscale, nullptr);
    // 4) channel mix + softmax
    mixsoftmax_kernel<<<dim3(128, 32), 512>>>(conv_w, conv_b);
    // 5) PV  (per (b,h): 256x64x256)
    gemm_mma<2, 64, 16><<<dim3(2, 384), 256>>>(nullptr, nullptr, nullptr, nullptr);
    // 6) output projection (M=8192, N=768, K=768)
    gemm_mma<3, 128, 48><<<dim3(6, 64), 256>>>(nullptr, proj_w, proj_b, out);
}

// round 17
// speedup vs baseline: 1.7815x; 1.7815x over previous
#include <cuda_runtime.h>
#include <cstdint>
#include <math.h>

#define BB 32
#define NN 256
#define HH 12
#define DD 64
#define CC 768

// ---------------- scratch (device globals; no runtime allocation) ----------------
__device__ float g_qin[BB*HH*NN*DD];      // (b,h,n,d)
__device__ float g_kin[BB*HH*NN*DD];      // (b,h,n,d)
__device__ float g_vt [BB*HH*DD*NN];      // (b,h,d,m)  V^T for PV GEMM
__device__ float g_qgr[BB*NN*CC];         // (b,n,h*64+d)
__device__ float g_kgr[BB*NN*CC];         // (b,n,h*64+d)
__device__ float g_sq [(size_t)BB*HH*NN*NN]; // gs*dots^2  (b,h,n,m)
__device__ float g_mix[(size_t)BB*HH*NN*NN]; // softmaxed P (b,o,n,m)
__device__ float g_ctx[BB*NN*CC];         // (b,n,h*64+d)

__device__ __forceinline__ float tf32_rna(float f) {
    uint32_t o;
    asm("cvt.rna.tf32.f32 %0, %1;" : "=r"(o) : "f"(f));
    return __uint_as_float(o);
}

__device__ __forceinline__ void mma_tf32(float* c, const float* a, const float* b) {
    asm volatile(
        "mma.sync.aligned.m16n8k8.row.col.f32.tf32.tf32.f32 "
        "{%0,%1,%2,%3}, {%4,%5,%6,%7}, {%8,%9}, {%0,%1,%2,%3};"
        : "+f"(c[0]), "+f"(c[1]), "+f"(c[2]), "+f"(c[3])
        : "r"(__float_as_uint(a[0])), "r"(__float_as_uint(a[1])),
          "r"(__float_as_uint(a[2])), "r"(__float_as_uint(a[3])),
          "r"(__float_as_uint(b[0])), "r"(__float_as_uint(b[1])));
}

// ======================= TF32 mma.sync GEMM (R3 structure — proven fast) =======================
template<int MODE, int TN, int NCH>
__global__ void __launch_bounds__(256) gemm_mma(const float* __restrict__ Ain,
                                                const float* __restrict__ Bin,
                                                const float* __restrict__ Xtra,
                                                float* __restrict__ Og)
{
    __shared__ float As[128 * 20];
    __shared__ float Bs[TN * 20];
    constexpr int NF = TN / 16;
    constexpr int NB4 = (TN * 4) / 256;

    const int tid = threadIdx.x, lane = tid & 31, wid = tid >> 5;
    const int wm = wid >> 1, wn = wid & 1;

    const float* Aba; const float* Bba; int sA, sB;
    if (MODE == 0) {
        Aba = Ain + (size_t)blockIdx.y * 128 * 768; sA = 768;
        Bba = Bin + (size_t)blockIdx.x * 128 * 768; sB = 768;
    } else if (MODE == 1) {
        int b = blockIdx.z, h = blockIdx.y;
        int nt = blockIdx.x >> 1, mt = blockIdx.x & 1;
        Aba = g_qgr + ((size_t)(b * 256 + nt * 128)) * 768 + h * 64; sA = 768;
        Bba = g_kgr + ((size_t)(b * 256 + mt * 128)) * 768 + h * 64; sB = 768;
    } else if (MODE == 2) {
        Aba = g_mix + (size_t)blockIdx.y * 65536 + (size_t)blockIdx.x * 128 * 256; sA = 256;
        Bba = g_vt + (size_t)blockIdx.y * 16384; sB = 256;
    } else {
        Aba = g_ctx + (size_t)blockIdx.y * 128 * 768; sA = 768;
        Bba = Bin + (size_t)blockIdx.x * 128 * 768; sB = 768;
    }

    float c[2][NF][4];
#pragma unroll
    for (int mf = 0; mf < 2; mf++)
#pragma unroll
        for (int nf = 0; nf < NF; nf++)
#pragma unroll
            for (int e = 0; e < 4; e++) c[mf][nf][e] = 0.f;

    float4 ra[2], rb[NB4];

#pragma unroll
    for (int i = 0; i < 2; i++) {
        int f = tid + i * 256; int r = f >> 2, cc = (f & 3) * 4;
        ra[i] = *(const float4*)(Aba + (size_t)r * sA + cc);
    }
#pragma unroll
    for (int i = 0; i < NB4; i++) {
        int f = tid + i * 256; int r = f >> 2, cc = (f & 3) * 4;
        rb[i] = *(const float4*)(Bba + (size_t)r * sB + cc);
    }

    for (int ch = 0; ch < NCH; ch++) {
#pragma unroll
        for (int i = 0; i < 2; i++) {
            int f = tid + i * 256; int r = f >> 2, cc = (f & 3) * 4;
            float4 v = ra[i];
            v.x = tf32_rna(v.x); v.y = tf32_rna(v.y); v.z = tf32_rna(v.z); v.w = tf32_rna(v.w);
            *(float4*)&As[r * 20 + cc] = v;
        }
#pragma unroll
        for (int i = 0; i < NB4; i++) {
            int f = tid + i * 256; int r = f >> 2, cc = (f & 3) * 4;
            float4 v = rb[i];
            v.x = tf32_rna(v.x); v.y = tf32_rna(v.y); v.z = tf32_rna(v.z); v.w = tf32_rna(v.w);
            *(float4*)&Bs[r * 20 + cc] = v;
        }
        __syncthreads();

        if (ch + 1 < NCH) {
            int ko = (ch + 1) * 16;
#pragma unroll
            for (int i = 0; i < 2; i++) {
                int f = tid + i * 256; int r = f >> 2, cc = (f & 3) * 4;
                ra[i] = *(const float4*)(Aba + (size_t)r * sA + ko + cc);
            }
#pragma unroll
            for (int i = 0; i < NB4; i++) {
                int f = tid + i * 256; int r = f >> 2, cc = (f & 3) * 4;
                rb[i] = *(const float4*)(Bba + (size_t)r * sB + ko + cc);
            }
        }

#pragma unroll
        for (int kk = 0; kk < 2; kk++) {
            const int ko = kk * 8;
            float a[2][4];
#pragma unroll
            for (int mf = 0; mf < 2; mf++) {
                int r0 = wm * 32 + mf * 16 + (lane >> 2);
                a[mf][0] = As[r0 * 20 + ko + (lane & 3)];
                a[mf][1] = As[(r0 + 8) * 20 + ko + (lane & 3)];
                a[mf][2] = As[r0 * 20 + ko + 4 + (lane & 3)];
                a[mf][3] = As[(r0 + 8) * 20 + ko + 4 + (lane & 3)];
            }
            float b[NF][2];
#pragma unroll
            for (int nf = 0; nf < NF; nf++) {
                int rr = wn * (TN / 2) + nf * 8 + (lane >> 2);
                b[nf][0] = Bs[rr * 20 + ko + (lane & 3)];
                b[nf][1] = Bs[rr * 20 + ko + 4 + (lane & 3)];
            }
#pragma unroll
            for (int mf = 0; mf < 2; mf++)
#pragma unroll
                for (int nf = 0; nf < NF; nf++)
                    mma_tf32(c[mf][nf], a[mf], b[nf]);
        }
        __syncthreads();
    }

#pragma unroll
    for (int mf = 0; mf < 2; mf++) {
#pragma unroll
        for (int nf = 0; nf < NF; nf++) {
            int rib0 = wm * 32 + mf * 16 + (lane >> 2);
            int cib = wn * (TN / 2) + nf * 8 + 2 * (lane & 3);
#pragma unroll
            for (int e = 0; e < 2; e++) {
                int rib = rib0 + e * 8;
                float v0 = c[mf][nf][e * 2], v1 = c[mf][nf][e * 2 + 1];
                if (MODE == 0) {
                    int colg = blockIdx.x * 128 + cib;
                    int rowg = blockIdx.y * 128 + rib;
                    int b = rowg >> 8, n = rowg & 255;
                    int which = colg / 768;
                    int rr = colg - which * 768;
                    int h = rr >> 6, dd = rr & 63;
                    v0 += Xtra[colg]; v1 += Xtra[colg + 1];
                    if (which == 0)
                        *(float2*)&g_qin[(((size_t)(b * 12 + h) * 256) + n) * 64 + dd] = make_float2(v0, v1);
                    else if (which == 1)
                        *(float2*)&g_kin[(((size_t)(b * 12 + h) * 256) + n) * 64 + dd] = make_float2(v0, v1);
                    else {
                        g_vt[(((size_t)(b * 12 + h)) * 64 + dd) * 256 + n] = v0;
                        g_vt[(((size_t)(b * 12 + h)) * 64 + dd + 1) * 256 + n] = v1;
                    }
                } else if (MODE == 1) {
                    float gs = Xtra[0];
                    int b = blockIdx.z, h = blockIdx.y;
                    int nt = blockIdx.x >> 1, mt = blockIdx.x & 1;
                    int n = nt * 128 + rib;
                    int m = mt * 128 + cib;
                    v0 = v0 * v0 * gs; v1 = v1 * v1 * gs;
                    *(float2*)&g_sq[(((size_t)(b * 12 + h) * 256) + n) * 256 + m] = make_float2(v0, v1);
                } else if (MODE == 2) {
                    int bh = blockIdx.y; int b = bh / 12, h = bh - b * 12;
                    int n = blockIdx.x * 128 + rib;
                    *(float2*)&g_ctx[((size_t)(b * 256 + n)) * 768 + h * 64 + cib] = make_float2(v0, v1);
                } else {
                    int colg = blockIdx.x * 128 + cib;
                    int rowg = blockIdx.y * 128 + rib;
                    v0 += Xtra[colg]; v1 += Xtra[colg + 1];
                    *(float2*)&Og[(size_t)rowg * 768 + colg] = make_float2(v0, v1);
                }
            }
        }
    }
}

// =====================================================================
// Batched QR: geqrf (rank-2 pairs, R14 trailing update) producing R,
// then Q = A * R^{-1} by per-thread forward substitution (replaces
// org2r — exact same Q in exact arithmetic, LAPACK signs preserved).
// =====================================================================
__global__ void __launch_bounds__(256) qr_kernel()
{
    extern __shared__ float sA[];   // 64 * 257
    __shared__ float s_tau[64];
    __shared__ float s_beta[64];
    __shared__ float s_binv[64];
    __shared__ float s_red[8];
    __shared__ float s_red2[8];
    __shared__ float s_alpha, s_vjp;

    const int tid = threadIdx.x;
    const int lane = tid & 31, warp = tid >> 5;

    int slab = blockIdx.x;
    int isk = (slab >= 384) ? 1 : 0;
    int s = slab - isk * 384;
    const float* src = (isk ? g_kin : g_qin) + (size_t)s * NN * DD;
    float* dst = isk ? g_kgr : g_qgr;
    int b = s / 12, h = s % 12;

    for (int idx = tid; idx < NN * DD; idx += 256) {
        int r = idx >> 6, c = idx & 63;
        sA[c * 257 + r] = src[idx];
    }
    __syncthreads();

    // ---------------- geqrf (pairs j, j+1) ----------------
    for (int j = 0; j < 64; j += 2) {
        float* colj  = sA + j * 257;
        float* colj1 = colj + 257;

        float x = (tid >= j) ? colj[tid] : 0.f;
        float alpha = colj[j];
        float ss = x * x;
#pragma unroll
        for (int o = 16; o > 0; o >>= 1) ss += __shfl_xor_sync(0xffffffffu, ss, o);
        if (lane == 0) s_red[warp] = ss;
        __syncthreads();
        float tot = 0.f;
#pragma unroll
        for (int w = 0; w < 8; w++) tot += s_red[w];
        float norm = sqrtf(tot);
        float tauj, scalj, betaj;
        if (norm < 1e-30f) { tauj = 0.f; scalj = 0.f; betaj = 1e-30f; }
        else {
            betaj = (alpha >= 0.f) ? -norm : norm;
            tauj = (betaj - alpha) / betaj;
            scalj = 1.f / (alpha - betaj);
        }
        if (tid == 0) { s_tau[j] = tauj; s_beta[j] = betaj; }
        if (tid > j)       colj[tid] = x * scalj;
        else if (tid == j) colj[tid] = 1.f;
        __syncthreads();

        float vj = colj[tid];
        float a1 = colj1[tid];
        float pd = (tid >= j) ? vj * a1 : 0.f;
#pragma unroll
        for (int o = 16; o > 0; o >>= 1) pd += __shfl_xor_sync(0xffffffffu, pd, o);
        if (lane == 0) s_red[warp] = pd;
        __syncthreads();
        float d1 = 0.f;
#pragma unroll
        for (int w = 0; w < 8; w++) d1 += s_red[w];
        float a1n = (tid >= j) ? a1 - tauj * d1 * vj : a1;
        float y  = (tid >= j + 1) ? a1n : 0.f;
        float ss2 = y * y;
        float sv  = (tid >= j + 1) ? vj * a1n : 0.f;
#pragma unroll
        for (int o = 16; o > 0; o >>= 1) {
            ss2 += __shfl_xor_sync(0xffffffffu, ss2, o);
            sv  += __shfl_xor_sync(0xffffffffu, sv, o);
        }
        if (lane == 0) { s_red[warp] = ss2; s_red2[warp] = sv; }
        if (tid == j + 1) { s_alpha = a1n; s_vjp = vj; }
        __syncthreads();
        float tot2 = 0.f, svs = 0.f;
#pragma unroll
        for (int w = 0; w < 8; w++) { tot2 += s_red[w]; svs += s_red2[w]; }
        float alpha2 = s_alpha, vjp = s_vjp;
        float norm2 = sqrtf(tot2);
        float tau1, scal1, beta2;
        if (norm2 < 1e-30f) { tau1 = 0.f; scal1 = 0.f; beta2 = 1e-30f; }
        else {
            beta2 = (alpha2 >= 0.f) ? -norm2 : norm2;
            tau1 = (beta2 - alpha2) / beta2;
            scal1 = 1.f / (alpha2 - beta2);
        }
        if (tid == 0) { s_tau[j + 1] = tau1; s_beta[j + 1] = beta2; }
        float s12 = vjp + scal1 * (svs - vjp * alpha2);
        float nv1;
        if (tid < j + 1)       nv1 = a1n;
        else if (tid == j + 1) nv1 = 1.f;
        else                   nv1 = a1n * scal1;
        colj1[tid] = nv1;
        __syncthreads();

        for (int c0 = j + 2 + warp * 2; c0 < 64; c0 += 16) {
            float vja[8], v1a[8];
#pragma unroll
            for (int k = 0; k < 8; k++) {
                int r = lane + k * 32;
                vja[k] = colj[r]; v1a[k] = colj1[r];
            }
            const int c1i = (c0 + 1 < 64) ? c0 + 1 : c0;
            const float* colcA = sA + c0 * 257;
            const float* colcB = sA + c1i * 257;
            float avA[8], avB[8];
            float d1A = 0.f, d2A = 0.f, d1B = 0.f, d2B = 0.f;
#pragma unroll
            for (int k = 0; k < 8; k++) {
                int r = lane + k * 32;
                avA[k] = colcA[r];
                avB[k] = colcB[r];
                if (r >= j)     { d1A += vja[k] * avA[k]; d1B += vja[k] * avB[k]; }
                if (r >= j + 1) { d2A += v1a[k] * avA[k]; d2B += v1a[k] * avB[k]; }
            }
#pragma unroll
            for (int o = 16; o > 0; o >>= 1) {
                d1A += __shfl_xor_sync(0xffffffffu, d1A, o);
                d2A += __shfl_xor_sync(0xffffffffu, d2A, o);
                d1B += __shfl_xor_sync(0xffffffffu, d1B, o);
                d2B += __shfl_xor_sync(0xffffffffu, d2B, o);
            }
            {
                float c1 = tauj * d1A;
                float c2 = tau1 * (d2A - c1 * s12);
                float* colc = sA + c0 * 257;
#pragma unroll
                for (int k = 0; k < 8; k++) {
                    int r = lane + k * 32;
                    if (r >= j) {
                        float nv = avA[k] - c1 * vja[k];
                        if (r >= j + 1) nv -= c2 * v1a[k];
                        colc[r] = nv;
                    }
                }
            }
            if (c0 + 1 < 64) {
                float c1 = tauj * d1B;
                float c2 = tau1 * (d2B - c1 * s12);
                float* colc = sA + (c0 + 1) * 257;
#pragma unroll
                for (int k = 0; k < 8; k++) {
                    int r = lane + k * 32;
                    if (r >= j) {
                        float nv = avB[k] - c1 * vja[k];
                        if (r >= j + 1) nv -= c2 * v1a[k];
                        colc[r] = nv;
                    }
                }
            }
        }
        __syncthreads();
    }

    // ---------------- Q = A * R^{-1} (forward substitution per row) ----------------
    // R[k][j] (k<j) = sA[j*257 + k]; R[j][j] = s_beta[j].
    if (tid < 64) s_binv[tid] = 1.f / s_beta[tid];
    __syncthreads();

    float q[64];
    {
        const float4* arow = (const float4*)(src + (size_t)tid * 64);
#pragma unroll
        for (int j4 = 0; j4 < 16; j4++) {
            float4 v = arow[j4];
            q[j4 * 4 + 0] = v.x; q[j4 * 4 + 1] = v.y;
            q[j4 * 4 + 2] = v.z; q[j4 * 4 + 3] = v.w;
        }
    }
#pragma unroll
    for (int j = 0; j < 64; j++) {
        float sacc = q[j];
#pragma unroll
        for (int k = 0; k < j; k++)
            sacc -= q[k] * sA[j * 257 + k];
        q[j] = sacc * s_binv[j];
    }

    // writeout to (b, n, h*64 + d)
    {
        float* drow = dst + (size_t)(b * 256 + tid) * 768 + h * 64;
#pragma unroll
        for (int j4 = 0; j4 < 16; j4++) {
            ((float4*)drow)[j4] = make_float4(q[j4 * 4 + 0], q[j4 * 4 + 1],
                                              q[j4 * 4 + 2], q[j4 * 4 + 3]);
        }
    }
}

// =====================================================================
// Fused channel-mix + softmax. Block handles (b, 2 n-rows), 512 threads.
// =====================================================================
__global__ void __launch_bounds__(512) mixsoftmax_kernel(const float* __restrict__ conv_w,
                                                         const float* __restrict__ conv_b)
{
    __shared__ float sm[24][260];
    __shared__ float s_w2[12][12];
    __shared__ float s_cb[12];

    int tid = threadIdx.x;
    int b = blockIdx.y;
    int n0 = blockIdx.x * 2;

    if (tid < 144) {
        int o = tid / 12, h = tid % 12;
        s_w2[o][h] = conv_w[o * 24 + h] + conv_w[o * 24 + 12 + h];
    }
    if (tid < 12) s_cb[tid] = conv_b[tid];
    __syncthreads();

    {
        int nn = tid >> 8, m = tid & 255;
        float v[12];
#pragma unroll
        for (int h = 0; h < 12; h++)
            v[h] = g_sq[(((size_t)(b * 12 + h) * 256) + n0 + nn) * 256 + m];
#pragma unroll
        for (int o = 0; o < 12; o++) {
            float acc = s_cb[o];
#pragma unroll
            for (int h = 0; h < 12; h++) acc += s_w2[o][h] * v[h];
            sm[nn * 12 + o][m] = acc;
        }
    }
    __syncthreads();

    int warp = tid >> 5, lane = tid & 31;
    for (int row = warp; row < 24; row += 16) {
        int nn = row / 12, o = row - nn * 12;
        const float* srcp = sm[row];
        float v[8];
        float mx = -1e30f;
#pragma unroll
        for (int i = 0; i < 8; i++) { v[i] = srcp[i * 32 + lane]; mx = fmaxf(mx, v[i]); }
#pragma unroll
        for (int off = 16; off > 0; off >>= 1) mx = fmaxf(mx, __shfl_xor_sync(0xffffffffu, mx, off));
        float smv = 0.f;
#pragma unroll
        for (int i = 0; i < 8; i++) { v[i] = expf(v[i] - mx); smv += v[i]; }
#pragma unroll
        for (int off = 16; off > 0; off >>= 1) smv += __shfl_xor_sync(0xffffffffu, smv, off);
        float inv = 1.f / smv;
        float* dstp = g_mix + (((size_t)(b * 12 + o) * 256) + n0 + nn) * 256;
#pragma unroll
        for (int i = 0; i < 8; i++) dstp[i * 32 + lane] = v[i] * inv;
    }
}

// =====================================================================
extern "C" void kernel_launch(void* const* d_in, const int* in_sizes, int n_in,
                              void* d_out, int out_size)
{
    const float* x      = (const float*)d_in[0];
    const float* qkv_w  = (const float*)d_in[1];
    const float* qkv_b  = (const float*)d_in[2];
    const float* gscale = (const float*)d_in[3];
    const float* conv_w = (const float*)d_in[4];
    const float* conv_b = (const float*)d_in[5];
    const float* proj_w = (const float*)d_in[6];
    const float* proj_b = (const float*)d_in[7];
    float* out = (float*)d_out;

    cudaFuncSetAttribute(qr_kernel, cudaFuncAttributeMaxDynamicSharedMemorySize, 64 * 257 * 4);

    // 1) QKV projection + scatter  (M=8192, N=2304, K=768)
    gemm_mma<0, 128, 48><<<dim3(18, 64), 256>>>(x, qkv_w, qkv_b, nullptr);
    // 2) batched QR: geqrf + triangular-solve Q formation
    qr_kernel<<<768, 256, 64 * 257 * 4>>>();
    // 3) Grassmann dots, squared+scaled  (per (b,h): 256x256x64)
    gemm_mma<1, 128, 4><<<dim3(4, 12, 32), 256>>>(nullptr, nullptr, gscale, nullptr);
    // 4) channel mix + softmax
    mixsoftmax_kernel<<<dim3(128, 32), 512>>>(conv_w, conv_b);
    // 5) PV  (per (b,h): 256x64x256)
    gemm_mma<2, 64, 16><<<dim3(2, 384), 256>>>(nullptr, nullptr, nullptr, nullptr);
    // 6) output projection (M=8192, N=768, K=768)
    gemm_mma<3, 128, 48><<<dim3(6, 64), 256>>>(nullptr, proj_w, proj_b, out);
}